// round 2
// baseline (speedup 1.0000x reference)
#include <cuda_runtime.h>
#include <cuda_bf16.h>

// Problem constants (from reference)
#define NN 100000
#define NE 1000000

// Scratch (float4 arrays => guaranteed 16B alignment for vector ld/red).
// Layer 1: per-node row of 56 floats: P1[o*4+k] (o<10,k<4) at [0..39], Q1[o] at [40..49]
// Layer 2: per-node row of 36 floats: P2[o*4+k] (o<7) at [0..27], Q2[o] at [28..34]
__device__ float4 g_P1[(size_t)NN * 14];  // 56 floats/row
__device__ float4 g_h1[(size_t)NN * 4];   // 16 floats/row, cols 0..9 used
__device__ float4 g_P2[(size_t)NN * 9];   // 36 floats/row
__device__ float4 g_h2[(size_t)NN * 2];   // 8 floats/row, cols 0..6 used
__device__ float  g_pool[8];
__device__ int    g_is64;                 // 1 if edge_index is int64, else int32

// ---------------------------------------------------------------------------
// k_detect: decide whether edge_index buffer holds int64 or int32 values.
// If the int64 interpretation of the first samples (both halves) is all in
// [0, n), it's int64; otherwise int32. (int32 data viewed as int64 fuses two
// random indices -> ~2^48 magnitude -> fails the range check.)
// ---------------------------------------------------------------------------
__global__ void k_detect(const void* __restrict__ ei, int ec, int n)
{
    if (threadIdx.x != 0 || blockIdx.x != 0) return;
    const long long* p = (const long long*)ei;
    int ok = 1;
    int m = ec < 64 ? ec : 64;
    for (int i = 0; i < m; i++) {
        long long a = p[i];
        long long b = p[(size_t)ec + i];
        if (a < 0 || a >= n || b < 0 || b >= n) { ok = 0; break; }
    }
    g_is64 = ok;
}

__device__ __forceinline__ void load_edge(const void* ei, int ec, int e,
                                          int& src, int& tgt)
{
    if (g_is64) {
        const long long* p = (const long long*)ei;
        src = (int)__ldg(&p[e]);
        tgt = (int)__ldg(&p[(size_t)ec + e]);
    } else {
        const int* p = (const int*)ei;
        src = __ldg(&p[e]);
        tgt = __ldg(&p[(size_t)ec + e]);
    }
}

// ---------------------------------------------------------------------------
// k_node1: per node n:
//   h1[n][o]   = sum_i x[n][i]*Wr1[i][o] + bb1[o]      (root term, init for scatter)
//   P1[n][o][k]= sum_i x[n][i]*W1e[i*10+o][k]
//   Q1[n][o]   = sum_i x[n][i]*b1e[i*10+o]
// ---------------------------------------------------------------------------
__global__ void k_node1(const float* __restrict__ x,
                        const float* __restrict__ W1e, const float* __restrict__ b1e,
                        const float* __restrict__ Wr1, const float* __restrict__ bb1,
                        int n)
{
    __shared__ float sW[720], sB[180], sWr[180], sBB[16];
    for (int i = threadIdx.x; i < 720; i += blockDim.x) sW[i] = W1e[i];
    for (int i = threadIdx.x; i < 180; i += blockDim.x) { sB[i] = b1e[i]; sWr[i] = Wr1[i]; }
    if (threadIdx.x < 10) sBB[threadIdx.x] = bb1[threadIdx.x];
    __syncthreads();

    int nd = blockIdx.x * blockDim.x + threadIdx.x;
    if (nd >= n) return;

    float xv[18];
    const float* xr = x + (size_t)nd * 18;
    #pragma unroll
    for (int i = 0; i < 18; i++) xv[i] = __ldg(&xr[i]);

    float* prow = (float*)(g_P1 + (size_t)nd * 14);
    float* hrow = (float*)(g_h1 + (size_t)nd * 4);

    #pragma unroll
    for (int o = 0; o < 10; o++) {
        float p0 = 0.f, p1 = 0.f, p2 = 0.f, p3 = 0.f, q = 0.f, h = 0.f;
        #pragma unroll
        for (int i = 0; i < 18; i++) {
            int r = i * 10 + o;
            float xi = xv[i];
            p0 += xi * sW[r * 4 + 0];
            p1 += xi * sW[r * 4 + 1];
            p2 += xi * sW[r * 4 + 2];
            p3 += xi * sW[r * 4 + 3];
            q  += xi * sB[r];
            h  += xi * sWr[r];
        }
        prow[o * 4 + 0] = p0;
        prow[o * 4 + 1] = p1;
        prow[o * 4 + 2] = p2;
        prow[o * 4 + 3] = p3;
        prow[40 + o]    = q;
        hrow[o]         = h + sBB[o];
    }
}

// ---------------------------------------------------------------------------
// k_edge1: per edge e: msg[o] = Q1[src][o] + sum_k attr[e][k]*P1[src][o][k]
//          scatter-add msg into h1[tgt][0..9] with vectorized red
// ---------------------------------------------------------------------------
__global__ void k_edge1(const void* __restrict__ ei,
                        const float4* __restrict__ attr, int ec)
{
    int e = blockIdx.x * blockDim.x + threadIdx.x;
    if (e >= ec) return;

    int src, tgt;
    load_edge(ei, ec, e, src, tgt);
    float4 a = __ldg(&attr[e]);

    const float* p = (const float*)(g_P1 + (size_t)src * 14);
    float4 q0 = *(const float4*)(p + 40);
    float4 q1 = *(const float4*)(p + 44);
    float2 q2 = *(const float2*)(p + 48);

    float m[10];
    #pragma unroll
    for (int o = 0; o < 10; o++) {
        float4 w = *(const float4*)(p + o * 4);
        m[o] = a.x * w.x + a.y * w.y + a.z * w.z + a.w * w.w;
    }
    m[0] += q0.x; m[1] += q0.y; m[2] += q0.z; m[3] += q0.w;
    m[4] += q1.x; m[5] += q1.y; m[6] += q1.z; m[7] += q1.w;
    m[8] += q2.x; m[9] += q2.y;

    float* h = (float*)(g_h1 + (size_t)tgt * 4);
    asm volatile("red.global.add.v4.f32 [%0], {%1,%2,%3,%4};"
                 :: "l"(h), "f"(m[0]), "f"(m[1]), "f"(m[2]), "f"(m[3]) : "memory");
    asm volatile("red.global.add.v4.f32 [%0], {%1,%2,%3,%4};"
                 :: "l"(h + 4), "f"(m[4]), "f"(m[5]), "f"(m[6]), "f"(m[7]) : "memory");
    asm volatile("red.global.add.v2.f32 [%0], {%1,%2};"
                 :: "l"(h + 8), "f"(m[8]), "f"(m[9]) : "memory");
}

// ---------------------------------------------------------------------------
// k_node2: per node n (reads finalized h1):
//   h2[n][o]   = sum_i h1[n][i]*Wr2[i][o] + bb2[o]
//   P2[n][o][k]= sum_i h1[n][i]*W2e[i*7+o][k]
//   Q2[n][o]   = sum_i h1[n][i]*b2e[i*7+o]
// Also re-zeroes the pooling accumulator (runs before k_pool each replay).
// ---------------------------------------------------------------------------
__global__ void k_node2(const float* __restrict__ W2e, const float* __restrict__ b2e,
                        const float* __restrict__ Wr2, const float* __restrict__ bb2,
                        int n)
{
    __shared__ float sW[280], sB[70], sWr[70], sBB[8];
    for (int i = threadIdx.x; i < 280; i += blockDim.x) sW[i] = W2e[i];
    for (int i = threadIdx.x; i < 70; i += blockDim.x) { sB[i] = b2e[i]; sWr[i] = Wr2[i]; }
    if (threadIdx.x < 7) sBB[threadIdx.x] = bb2[threadIdx.x];
    __syncthreads();

    if (blockIdx.x == 0 && threadIdx.x < 8) g_pool[threadIdx.x] = 0.f;

    int nd = blockIdx.x * blockDim.x + threadIdx.x;
    if (nd >= n) return;

    float hv[10];
    const float* hr = (const float*)(g_h1 + (size_t)nd * 4);
    #pragma unroll
    for (int i = 0; i < 10; i++) hv[i] = hr[i];

    float* prow = (float*)(g_P2 + (size_t)nd * 9);
    float* orow = (float*)(g_h2 + (size_t)nd * 2);

    #pragma unroll
    for (int o = 0; o < 7; o++) {
        float p0 = 0.f, p1 = 0.f, p2 = 0.f, p3 = 0.f, q = 0.f, h = 0.f;
        #pragma unroll
        for (int i = 0; i < 10; i++) {
            int r = i * 7 + o;
            float hi = hv[i];
            p0 += hi * sW[r * 4 + 0];
            p1 += hi * sW[r * 4 + 1];
            p2 += hi * sW[r * 4 + 2];
            p3 += hi * sW[r * 4 + 3];
            q  += hi * sB[r];
            h  += hi * sWr[r];
        }
        prow[o * 4 + 0] = p0;
        prow[o * 4 + 1] = p1;
        prow[o * 4 + 2] = p2;
        prow[o * 4 + 3] = p3;
        prow[28 + o]    = q;
        orow[o]         = h + sBB[o];
    }
    orow[7] = 0.f;
}

// ---------------------------------------------------------------------------
// k_edge2: per edge: msg[o] = Q2[src][o] + sum_k attr[e][k]*P2[src][o][k]
// ---------------------------------------------------------------------------
__global__ void k_edge2(const void* __restrict__ ei,
                        const float4* __restrict__ attr, int ec)
{
    int e = blockIdx.x * blockDim.x + threadIdx.x;
    if (e >= ec) return;

    int src, tgt;
    load_edge(ei, ec, e, src, tgt);
    float4 a = __ldg(&attr[e]);

    const float* p = (const float*)(g_P2 + (size_t)src * 9);
    float4 q0 = *(const float4*)(p + 28);
    float2 q1 = *(const float2*)(p + 32);
    float  q2 = p[34];

    float m[7];
    #pragma unroll
    for (int o = 0; o < 7; o++) {
        float4 w = *(const float4*)(p + o * 4);
        m[o] = a.x * w.x + a.y * w.y + a.z * w.z + a.w * w.w;
    }
    m[0] += q0.x; m[1] += q0.y; m[2] += q0.z; m[3] += q0.w;
    m[4] += q1.x; m[5] += q1.y; m[6] += q2;

    float* h = (float*)(g_h2 + (size_t)tgt * 2);
    asm volatile("red.global.add.v4.f32 [%0], {%1,%2,%3,%4};"
                 :: "l"(h), "f"(m[0]), "f"(m[1]), "f"(m[2]), "f"(m[3]) : "memory");
    asm volatile("red.global.add.v2.f32 [%0], {%1,%2};"
                 :: "l"(h + 4), "f"(m[4]), "f"(m[5]) : "memory");
    asm volatile("red.global.add.f32 [%0], %1;"
                 :: "l"(h + 6), "f"(m[6]) : "memory");
}

// ---------------------------------------------------------------------------
// k_pool: sum h2 over nodes into g_pool[0..6]
// ---------------------------------------------------------------------------
__global__ void k_pool(int n)
{
    float s[7];
    #pragma unroll
    for (int k = 0; k < 7; k++) s[k] = 0.f;

    for (int nd = blockIdx.x * blockDim.x + threadIdx.x; nd < n;
         nd += gridDim.x * blockDim.x) {
        const float* h = (const float*)(g_h2 + (size_t)nd * 2);
        #pragma unroll
        for (int k = 0; k < 7; k++) s[k] += h[k];
    }

    // warp reduce
    #pragma unroll
    for (int k = 0; k < 7; k++) {
        #pragma unroll
        for (int off = 16; off > 0; off >>= 1)
            s[k] += __shfl_down_sync(0xffffffffu, s[k], off);
    }

    __shared__ float sh[8][8];
    int w = threadIdx.x >> 5, l = threadIdx.x & 31;
    if (l == 0) {
        #pragma unroll
        for (int k = 0; k < 7; k++) sh[w][k] = s[k];
    }
    __syncthreads();
    if (threadIdx.x == 0) {
        int nwarps = blockDim.x >> 5;
        float t[7];
        #pragma unroll
        for (int k = 0; k < 7; k++) t[k] = 0.f;
        for (int ww = 0; ww < nwarps; ww++) {
            #pragma unroll
            for (int k = 0; k < 7; k++) t[k] += sh[ww][k];
        }
        #pragma unroll
        for (int k = 0; k < 7; k++) atomicAdd(&g_pool[k], t[k]);
    }
}

// ---------------------------------------------------------------------------
// k_final: mean pool -> MLP (7->20 relu ->10 relu ->1) -> sigmoid
// ---------------------------------------------------------------------------
__global__ void k_final(const float* __restrict__ w1, const float* __restrict__ bw1,
                        const float* __restrict__ w2, const float* __restrict__ bw2,
                        const float* __restrict__ w3, const float* __restrict__ bw3,
                        float* __restrict__ out, int n, int out_size)
{
    if (threadIdx.x != 0 || blockIdx.x != 0) return;
    float g[7];
    float inv = 1.0f / (float)n;
    #pragma unroll
    for (int k = 0; k < 7; k++) g[k] = g_pool[k] * inv;

    float g1[20];
    for (int j = 0; j < 20; j++) {
        float v = bw1[j];
        #pragma unroll
        for (int k = 0; k < 7; k++) v += g[k] * w1[j * 7 + k];
        g1[j] = v > 0.f ? v : 0.f;
    }
    float g2[10];
    for (int j = 0; j < 10; j++) {
        float v = bw2[j];
        #pragma unroll
        for (int k = 0; k < 20; k++) v += g1[k] * w2[j * 20 + k];
        g2[j] = v > 0.f ? v : 0.f;
    }
    float z = bw3[0];
    #pragma unroll
    for (int k = 0; k < 10; k++) z += g2[k] * w3[k];
    float r = 1.0f / (1.0f + expf(-z));
    for (int i = 0; i < out_size; i++) out[i] = r;
}

// ---------------------------------------------------------------------------
extern "C" void kernel_launch(void* const* d_in, const int* in_sizes, int n_in,
                              void* d_out, int out_size)
{
    const float* x    = (const float*)d_in[0];
    const void*  ei   = d_in[1];
    const float4* attr = (const float4*)d_in[2];
    const float* W1e = (const float*)d_in[3];
    const float* b1e = (const float*)d_in[4];
    const float* Wr1 = (const float*)d_in[5];
    const float* bb1 = (const float*)d_in[6];
    const float* W2e = (const float*)d_in[7];
    const float* b2e = (const float*)d_in[8];
    const float* Wr2 = (const float*)d_in[9];
    const float* bb2 = (const float*)d_in[10];
    const float* w1  = (const float*)d_in[11];
    const float* bw1 = (const float*)d_in[12];
    const float* w2  = (const float*)d_in[13];
    const float* bw2 = (const float*)d_in[14];
    const float* w3  = (const float*)d_in[15];
    const float* bw3 = (const float*)d_in[16];

    int n = in_sizes[0] / 18;
    int e = in_sizes[2] / 4;
    if (n > NN) n = NN;
    if (e > NE) e = NE;

    // If edge_index is int64, in_sizes[1] counts int64 elements (2*E). If the
    // harness stored it as int32, the element count is the same. Either way,
    // detection is done on-device.
    const int T = 256;
    k_detect<<<1, 1>>>(ei, e, n);
    k_node1<<<(n + T - 1) / T, T>>>(x, W1e, b1e, Wr1, bb1, n);
    k_edge1<<<(e + T - 1) / T, T>>>(ei, attr, e);
    k_node2<<<(n + T - 1) / T, T>>>(W2e, b2e, Wr2, bb2, n);
    k_edge2<<<(e + T - 1) / T, T>>>(ei, attr, e);
    k_pool<<<444, T>>>(n);
    k_final<<<1, 1>>>(w1, bw1, w2, bw2, w3, bw3, (float*)d_out, n, out_size);
}

// round 3
// speedup vs baseline: 1.4214x; 1.4214x over previous
#include <cuda_runtime.h>
#include <cuda_bf16.h>

#define NN 100000
#define NE 1000000

// Scratch (float4 arrays => guaranteed 16B alignment).
// P1 row: 56 floats/node: P1[o*4+k] (o<10,k<4) at [0..39], Q1[o] at [40..49]
// h1 row: 16 floats/node (cols 0..9 used)
// S  row: 8 floats/node: attr-sum[0..3], out-degree at [4]
__device__ float4 g_P1[(size_t)NN * 14];
__device__ float4 g_h1[(size_t)NN * 4];
__device__ float4 g_S [(size_t)NN * 2];
__device__ float  g_red[64];   // v[10] at 0..9, T[i*5+k] (10x5) at 16..65? -> packed below
__device__ int    g_is64;

// g_red layout: v[i] = g_red[i] (i<10), T[i][k] = g_red[10 + i*5 + k] (k<5; k==4 is deg-weighted)
// total 10 + 50 = 60 floats

// ---------------------------------------------------------------------------
// k_detect: parallel dtype sniff for edge_index (int64 vs int32).
// ---------------------------------------------------------------------------
__global__ void k_detect(const void* __restrict__ ei, int ec, int n)
{
    __shared__ int ok;
    int tid = threadIdx.x;
    if (tid == 0) ok = 1;
    __syncthreads();
    const long long* p = (const long long*)ei;
    int m = ec < 64 ? ec : 64;
    if (tid < 2 * m) {
        long long v = (tid < m) ? p[tid] : p[(size_t)ec + (tid - m)];
        if (v < 0 || v >= n) ok = 0;
    }
    __syncthreads();
    if (tid == 0) g_is64 = ok;
}

__device__ __forceinline__ void load_edge(const void* ei, int ec, int e,
                                          int& src, int& tgt)
{
    if (g_is64) {
        const long long* p = (const long long*)ei;
        src = (int)__ldg(&p[e]);
        tgt = (int)__ldg(&p[(size_t)ec + e]);
    } else {
        const int* p = (const int*)ei;
        src = __ldg(&p[e]);
        tgt = __ldg(&p[(size_t)ec + e]);
    }
}

// ---------------------------------------------------------------------------
// k_node1: 2 threads per node (half = low bit), each computes 5 output chans:
//   h1[n][o]   = sum_i x[n][i]*Wr1[i][o] + bb1[o]   (root init for scatter)
//   P1[n][o][k]= sum_i x[n][i]*W1e[i*10+o][k]
//   Q1[n][o]   = sum_i x[n][i]*b1e[i*10+o]
// Also zeroes S rows and (block 0) the g_red accumulator.
// ---------------------------------------------------------------------------
__global__ void k_node1(const float* __restrict__ x,
                        const float* __restrict__ W1e, const float* __restrict__ b1e,
                        const float* __restrict__ Wr1, const float* __restrict__ bb1,
                        int n)
{
    __shared__ float sW[720], sB[180], sWr[180], sBB[16];
    for (int i = threadIdx.x; i < 720; i += blockDim.x) sW[i] = W1e[i];
    for (int i = threadIdx.x; i < 180; i += blockDim.x) { sB[i] = b1e[i]; sWr[i] = Wr1[i]; }
    if (threadIdx.x < 10) sBB[threadIdx.x] = bb1[threadIdx.x];
    if (blockIdx.x == 0 && threadIdx.x < 64) g_red[threadIdx.x] = 0.f;
    __syncthreads();

    int gid  = blockIdx.x * blockDim.x + threadIdx.x;
    int nd   = gid >> 1;
    int half = gid & 1;
    if (nd >= n) return;

    float xv[18];
    const float* xr = x + (size_t)nd * 18;
    #pragma unroll
    for (int i = 0; i < 18; i++) xv[i] = __ldg(&xr[i]);

    float4* prow4 = (float4*)(g_P1 + (size_t)nd * 14);
    float*  prow  = (float*)prow4;
    float*  hrow  = (float*)(g_h1 + (size_t)nd * 4);
    float*  srow  = (float*)(g_S  + (size_t)nd * 2);

    if (half == 0) {
        *(float4*)srow = make_float4(0.f, 0.f, 0.f, 0.f);
    } else {
        srow[4] = 0.f;
    }

    int o0 = half * 5;
    #pragma unroll
    for (int oo = 0; oo < 5; oo++) {
        int o = o0 + oo;
        float p0 = 0.f, p1 = 0.f, p2 = 0.f, p3 = 0.f, q = 0.f, h = 0.f;
        #pragma unroll
        for (int i = 0; i < 18; i++) {
            int r = i * 10 + o;
            float xi = xv[i];
            p0 += xi * sW[r * 4 + 0];
            p1 += xi * sW[r * 4 + 1];
            p2 += xi * sW[r * 4 + 2];
            p3 += xi * sW[r * 4 + 3];
            q  += xi * sB[r];
            h  += xi * sWr[r];
        }
        prow4[o]     = make_float4(p0, p1, p2, p3);
        prow[40 + o] = q;
        hrow[o]      = h + sBB[o];
    }
}

// ---------------------------------------------------------------------------
// k_edge1: per edge e:
//   msg[o] = Q1[src][o] + sum_k attr[e][k]*P1[src][o][k] -> RED into h1[tgt]
//   also RED attr into S[src][0..3] and 1.0 into S[src][4] (out-degree)
// ---------------------------------------------------------------------------
__global__ void k_edge1(const void* __restrict__ ei,
                        const float4* __restrict__ attr, int ec)
{
    int e = blockIdx.x * blockDim.x + threadIdx.x;
    if (e >= ec) return;

    int src, tgt;
    load_edge(ei, ec, e, src, tgt);
    float4 a = __ldg(&attr[e]);

    const float* p = (const float*)(g_P1 + (size_t)src * 14);
    float4 q0 = *(const float4*)(p + 40);
    float4 q1 = *(const float4*)(p + 44);
    float2 q2 = *(const float2*)(p + 48);

    float m[10];
    #pragma unroll
    for (int o = 0; o < 10; o++) {
        float4 w = *(const float4*)(p + o * 4);
        m[o] = a.x * w.x + a.y * w.y + a.z * w.z + a.w * w.w;
    }
    m[0] += q0.x; m[1] += q0.y; m[2] += q0.z; m[3] += q0.w;
    m[4] += q1.x; m[5] += q1.y; m[6] += q1.z; m[7] += q1.w;
    m[8] += q2.x; m[9] += q2.y;

    float* h = (float*)(g_h1 + (size_t)tgt * 4);
    asm volatile("red.global.add.v4.f32 [%0], {%1,%2,%3,%4};"
                 :: "l"(h), "f"(m[0]), "f"(m[1]), "f"(m[2]), "f"(m[3]) : "memory");
    asm volatile("red.global.add.v4.f32 [%0], {%1,%2,%3,%4};"
                 :: "l"(h + 4), "f"(m[4]), "f"(m[5]), "f"(m[6]), "f"(m[7]) : "memory");
    asm volatile("red.global.add.v2.f32 [%0], {%1,%2};"
                 :: "l"(h + 8), "f"(m[8]), "f"(m[9]) : "memory");

    float* s = (float*)(g_S + (size_t)src * 2);
    asm volatile("red.global.add.v4.f32 [%0], {%1,%2,%3,%4};"
                 :: "l"(s), "f"(a.x), "f"(a.y), "f"(a.z), "f"(a.w) : "memory");
    asm volatile("red.global.add.f32 [%0], %1;"
                 :: "l"(s + 4), "f"(1.0f) : "memory");
}

// ---------------------------------------------------------------------------
// k_reduce2: over nodes, accumulate
//   v[i]    = sum_n h1[n][i]                  (i<10)
//   T[i][k] = sum_n h1[n][i] * S[n][k]        (k<5; S[4]=deg)
// into g_red via block-level reduction + atomics.
// ---------------------------------------------------------------------------
__global__ void k_reduce2(int n)
{
    float v[10];
    float T[50];
    #pragma unroll
    for (int i = 0; i < 10; i++) v[i] = 0.f;
    #pragma unroll
    for (int i = 0; i < 50; i++) T[i] = 0.f;

    for (int nd = blockIdx.x * blockDim.x + threadIdx.x; nd < n;
         nd += gridDim.x * blockDim.x) {
        const float* hr = (const float*)(g_h1 + (size_t)nd * 4);
        const float* sr = (const float*)(g_S  + (size_t)nd * 2);
        float4 ha = *(const float4*)hr;
        float4 hb = *(const float4*)(hr + 4);
        float2 hc = *(const float2*)(hr + 8);
        float hv[10] = {ha.x, ha.y, ha.z, ha.w, hb.x, hb.y, hb.z, hb.w, hc.x, hc.y};
        float4 s4 = *(const float4*)sr;
        float  sd = sr[4];
        float sv[5] = {s4.x, s4.y, s4.z, s4.w, sd};
        #pragma unroll
        for (int i = 0; i < 10; i++) {
            float hi = hv[i];
            v[i] += hi;
            #pragma unroll
            for (int k = 0; k < 5; k++) T[i * 5 + k] += hi * sv[k];
        }
    }

    // warp reduce all 60
    #pragma unroll
    for (int off = 16; off > 0; off >>= 1) {
        #pragma unroll
        for (int i = 0; i < 10; i++) v[i] += __shfl_down_sync(0xffffffffu, v[i], off);
        #pragma unroll
        for (int i = 0; i < 50; i++) T[i] += __shfl_down_sync(0xffffffffu, T[i], off);
    }

    __shared__ float sh[8][64];
    int w = threadIdx.x >> 5, l = threadIdx.x & 31;
    if (l == 0) {
        #pragma unroll
        for (int i = 0; i < 10; i++) sh[w][i] = v[i];
        #pragma unroll
        for (int i = 0; i < 50; i++) sh[w][10 + i] = T[i];
    }
    __syncthreads();
    int nwarps = blockDim.x >> 5;
    if (threadIdx.x < 60) {
        float t = 0.f;
        for (int ww = 0; ww < nwarps; ww++) t += sh[ww][threadIdx.x];
        atomicAdd(&g_red[threadIdx.x], t);
    }
}

// ---------------------------------------------------------------------------
// k_final (1 warp): assemble layer-2 sum, mean pool, MLP, sigmoid.
//   sum_h2[o] = v@Wr2[:,o] + N*bb2[o]
//             + sum_{i,k<4} T[i][k]*W2e[i*7+o, k] + sum_i T[i][4]*b2e[i*7+o]
// ---------------------------------------------------------------------------
__global__ void k_final(const float* __restrict__ Wr2, const float* __restrict__ bb2,
                        const float* __restrict__ W2e, const float* __restrict__ b2e,
                        const float* __restrict__ w1, const float* __restrict__ bw1,
                        const float* __restrict__ w2, const float* __restrict__ bw2,
                        const float* __restrict__ w3, const float* __restrict__ bw3,
                        float* __restrict__ out, int n, int out_size)
{
    __shared__ float g[8];
    int lane = threadIdx.x;
    float invn = 1.0f / (float)n;

    if (lane < 7) {
        int o = lane;
        float s = (float)n * bb2[o];
        #pragma unroll
        for (int i = 0; i < 10; i++) {
            float vi = g_red[i];
            s += vi * Wr2[i * 7 + o];                 // root term
            float* Ti = &g_red[10 + i * 5];
            int r = i * 7 + o;
            #pragma unroll
            for (int k = 0; k < 4; k++) s += Ti[k] * W2e[r * 4 + k];
            s += Ti[4] * b2e[r];                      // per-edge bias term
        }
        g[o] = s * invn;
    }
    __syncwarp();

    if (lane == 0) {
        float gg[7];
        #pragma unroll
        for (int k = 0; k < 7; k++) gg[k] = g[k];
        float g1[20];
        for (int j = 0; j < 20; j++) {
            float v = bw1[j];
            #pragma unroll
            for (int k = 0; k < 7; k++) v += gg[k] * w1[j * 7 + k];
            g1[j] = v > 0.f ? v : 0.f;
        }
        float g2[10];
        for (int j = 0; j < 10; j++) {
            float v = bw2[j];
            #pragma unroll
            for (int k = 0; k < 20; k++) v += g1[k] * w2[j * 20 + k];
            g2[j] = v > 0.f ? v : 0.f;
        }
        float z = bw3[0];
        #pragma unroll
        for (int k = 0; k < 10; k++) z += g2[k] * w3[k];
        float r = 1.0f / (1.0f + expf(-z));
        for (int i = 0; i < out_size; i++) out[i] = r;
    }
}

// ---------------------------------------------------------------------------
extern "C" void kernel_launch(void* const* d_in, const int* in_sizes, int n_in,
                              void* d_out, int out_size)
{
    const float*  x    = (const float*)d_in[0];
    const void*   ei   = d_in[1];
    const float4* attr = (const float4*)d_in[2];
    const float* W1e = (const float*)d_in[3];
    const float* b1e = (const float*)d_in[4];
    const float* Wr1 = (const float*)d_in[5];
    const float* bb1 = (const float*)d_in[6];
    const float* W2e = (const float*)d_in[7];
    const float* b2e = (const float*)d_in[8];
    const float* Wr2 = (const float*)d_in[9];
    const float* bb2 = (const float*)d_in[10];
    const float* w1  = (const float*)d_in[11];
    const float* bw1 = (const float*)d_in[12];
    const float* w2  = (const float*)d_in[13];
    const float* bw2 = (const float*)d_in[14];
    const float* w3  = (const float*)d_in[15];
    const float* bw3 = (const float*)d_in[16];

    int n = in_sizes[0] / 18;
    int e = in_sizes[2] / 4;
    if (n > NN) n = NN;
    if (e > NE) e = NE;

    const int T = 256;
    k_detect<<<1, 128>>>(ei, e, n);
    k_node1<<<(2 * n + T - 1) / T, T>>>(x, W1e, b1e, Wr1, bb1, n);
    k_edge1<<<(e + T - 1) / T, T>>>(ei, attr, e);
    k_reduce2<<<256, T>>>(n);
    k_final<<<1, 32>>>(Wr2, bb2, W2e, b2e, w1, bw1, w2, bw2, w3, bw3,
                       (float*)d_out, n, out_size);
}

// round 4
// speedup vs baseline: 1.5155x; 1.0662x over previous
#include <cuda_runtime.h>
#include <cuda_fp16.h>

#define NN 100000
#define NE 1000000

// Scratch.
// P1h: fp16 table, one 128B row per node (64 halfs):
//   halfs[0..39]  = P1[o*4+k] (o<10, k<4)
//   halfs[40..49] = Q1[o]
// h1 row: 16 floats/node (cols 0..9 used) -- f32 scatter target
// S  row: 8 floats/node: attr-sum[0..3], out-degree at [4]
__device__ float4 g_P1h[(size_t)NN * 8];   // 128B rows, 16B aligned
__device__ float4 g_h1 [(size_t)NN * 4];
__device__ float4 g_S  [(size_t)NN * 2];
__device__ float  g_red[64];  // v[i]=g_red[i] (i<10); T[i][k]=g_red[10+i*5+k] (k<5, k==4 deg)
__device__ int    g_is64;

// ---------------------------------------------------------------------------
// k_detect: parallel dtype sniff for edge_index (int64 vs int32).
// ---------------------------------------------------------------------------
__global__ void k_detect(const void* __restrict__ ei, int ec, int n)
{
    __shared__ int ok;
    int tid = threadIdx.x;
    if (tid == 0) ok = 1;
    __syncthreads();
    const long long* p = (const long long*)ei;
    int m = ec < 64 ? ec : 64;
    if (tid < 2 * m) {
        long long v = (tid < m) ? p[tid] : p[(size_t)ec + (tid - m)];
        if (v < 0 || v >= n) ok = 0;
    }
    __syncthreads();
    if (tid == 0) g_is64 = ok;
}

__device__ __forceinline__ void load_edge(const void* ei, int ec, int e,
                                          int& src, int& tgt)
{
    if (g_is64) {
        const long long* p = (const long long*)ei;
        src = (int)__ldg(&p[e]);
        tgt = (int)__ldg(&p[(size_t)ec + e]);
    } else {
        const int* p = (const int*)ei;
        src = __ldg(&p[e]);
        tgt = __ldg(&p[(size_t)ec + e]);
    }
}

// ---------------------------------------------------------------------------
// k_node1: 2 threads per node (half = low bit), each computes 5 output chans:
//   h1[n][o]   = sum_i x[n][i]*Wr1[i][o] + bb1[o]   (root init for scatter, f32)
//   P1h[n][o][k] (fp16), Q1h[n][o] (fp16)
// Also zeroes S rows and (block 0) the g_red accumulator.
// ---------------------------------------------------------------------------
__global__ void k_node1(const float* __restrict__ x,
                        const float* __restrict__ W1e, const float* __restrict__ b1e,
                        const float* __restrict__ Wr1, const float* __restrict__ bb1,
                        int n)
{
    __shared__ float sW[720], sB[180], sWr[180], sBB[16];
    for (int i = threadIdx.x; i < 720; i += blockDim.x) sW[i] = W1e[i];
    for (int i = threadIdx.x; i < 180; i += blockDim.x) { sB[i] = b1e[i]; sWr[i] = Wr1[i]; }
    if (threadIdx.x < 10) sBB[threadIdx.x] = bb1[threadIdx.x];
    if (blockIdx.x == 0 && threadIdx.x < 64) g_red[threadIdx.x] = 0.f;
    __syncthreads();

    int gid  = blockIdx.x * blockDim.x + threadIdx.x;
    int nd   = gid >> 1;
    int half = gid & 1;
    if (nd >= n) return;

    float xv[18];
    const float* xr = x + (size_t)nd * 18;
    #pragma unroll
    for (int i = 0; i < 18; i++) xv[i] = __ldg(&xr[i]);

    __half2* prow = (__half2*)(g_P1h + (size_t)nd * 8);
    __half*  qrow = (__half*)prow;            // halfs[40..49]
    float*   hrow = (float*)(g_h1 + (size_t)nd * 4);
    float*   srow = (float*)(g_S  + (size_t)nd * 2);

    if (half == 0) {
        *(float4*)srow = make_float4(0.f, 0.f, 0.f, 0.f);
    } else {
        srow[4] = 0.f;
    }

    int o0 = half * 5;
    #pragma unroll
    for (int oo = 0; oo < 5; oo++) {
        int o = o0 + oo;
        float p0 = 0.f, p1 = 0.f, p2 = 0.f, p3 = 0.f, q = 0.f, h = 0.f;
        #pragma unroll
        for (int i = 0; i < 18; i++) {
            int r = i * 10 + o;
            float xi = xv[i];
            p0 += xi * sW[r * 4 + 0];
            p1 += xi * sW[r * 4 + 1];
            p2 += xi * sW[r * 4 + 2];
            p3 += xi * sW[r * 4 + 3];
            q  += xi * sB[r];
            h  += xi * sWr[r];
        }
        prow[o * 2 + 0] = __floats2half2_rn(p0, p1);
        prow[o * 2 + 1] = __floats2half2_rn(p2, p3);
        qrow[40 + o]    = __float2half_rn(q);
        hrow[o]         = h + sBB[o];
    }
}

// ---------------------------------------------------------------------------
// k_edge1: per edge e (single 128B-line gather):
//   msg[o] = Q1[src][o] + sum_k attr[e][k]*P1[src][o][k]  -> RED into h1[tgt]
//   also RED attr into S[src][0..3] and 1.0 into S[src][4]
// ---------------------------------------------------------------------------
__global__ void k_edge1(const void* __restrict__ ei,
                        const float4* __restrict__ attr, int ec)
{
    int e = blockIdx.x * blockDim.x + threadIdx.x;
    if (e >= ec) return;

    int src, tgt;
    load_edge(ei, ec, e, src, tgt);
    float4 a = __ldg(&attr[e]);

    const float4* r = g_P1h + (size_t)src * 8;
    float4 raw[7];
    #pragma unroll
    for (int i = 0; i < 6; i++) raw[i] = __ldg(&r[i]);       // halfs 0..47
    raw[6].x = __ldg((const float*)r + 24);                  // halfs 48,49
    const __half2* hp = (const __half2*)raw;

    float m[10];
    #pragma unroll
    for (int o = 0; o < 10; o++) {
        float2 pab = __half22float2(hp[o * 2 + 0]);
        float2 pcd = __half22float2(hp[o * 2 + 1]);
        m[o] = a.x * pab.x + a.y * pab.y + a.z * pcd.x + a.w * pcd.y;
    }
    // Q: halfs 40..49 => hp[20..23] + raw[6].x (as half2)
    #pragma unroll
    for (int j = 0; j < 5; j++) {
        float2 q2 = __half22float2(hp[20 + j]);
        m[j * 2 + 0] += q2.x;
        m[j * 2 + 1] += q2.y;
    }

    float* h = (float*)(g_h1 + (size_t)tgt * 4);
    asm volatile("red.global.add.v4.f32 [%0], {%1,%2,%3,%4};"
                 :: "l"(h), "f"(m[0]), "f"(m[1]), "f"(m[2]), "f"(m[3]) : "memory");
    asm volatile("red.global.add.v4.f32 [%0], {%1,%2,%3,%4};"
                 :: "l"(h + 4), "f"(m[4]), "f"(m[5]), "f"(m[6]), "f"(m[7]) : "memory");
    asm volatile("red.global.add.v2.f32 [%0], {%1,%2};"
                 :: "l"(h + 8), "f"(m[8]), "f"(m[9]) : "memory");

    float* s = (float*)(g_S + (size_t)src * 2);
    asm volatile("red.global.add.v4.f32 [%0], {%1,%2,%3,%4};"
                 :: "l"(s), "f"(a.x), "f"(a.y), "f"(a.z), "f"(a.w) : "memory");
    asm volatile("red.global.add.f32 [%0], %1;"
                 :: "l"(s + 4), "f"(1.0f) : "memory");
}

// ---------------------------------------------------------------------------
// k_reduce2: over nodes, accumulate
//   v[i]    = sum_n h1[n][i]                  (i<10)
//   T[i][k] = sum_n h1[n][i] * S[n][k]        (k<5; S[4]=deg)
// ---------------------------------------------------------------------------
__global__ void k_reduce2(int n)
{
    float v[10];
    float T[50];
    #pragma unroll
    for (int i = 0; i < 10; i++) v[i] = 0.f;
    #pragma unroll
    for (int i = 0; i < 50; i++) T[i] = 0.f;

    for (int nd = blockIdx.x * blockDim.x + threadIdx.x; nd < n;
         nd += gridDim.x * blockDim.x) {
        const float* hr = (const float*)(g_h1 + (size_t)nd * 4);
        const float* sr = (const float*)(g_S  + (size_t)nd * 2);
        float4 ha = *(const float4*)hr;
        float4 hb = *(const float4*)(hr + 4);
        float2 hc = *(const float2*)(hr + 8);
        float hv[10] = {ha.x, ha.y, ha.z, ha.w, hb.x, hb.y, hb.z, hb.w, hc.x, hc.y};
        float4 s4 = *(const float4*)sr;
        float  sd = sr[4];
        float sv[5] = {s4.x, s4.y, s4.z, s4.w, sd};
        #pragma unroll
        for (int i = 0; i < 10; i++) {
            float hi = hv[i];
            v[i] += hi;
            #pragma unroll
            for (int k = 0; k < 5; k++) T[i * 5 + k] += hi * sv[k];
        }
    }

    #pragma unroll
    for (int off = 16; off > 0; off >>= 1) {
        #pragma unroll
        for (int i = 0; i < 10; i++) v[i] += __shfl_down_sync(0xffffffffu, v[i], off);
        #pragma unroll
        for (int i = 0; i < 50; i++) T[i] += __shfl_down_sync(0xffffffffu, T[i], off);
    }

    __shared__ float sh[8][64];
    int w = threadIdx.x >> 5, l = threadIdx.x & 31;
    if (l == 0) {
        #pragma unroll
        for (int i = 0; i < 10; i++) sh[w][i] = v[i];
        #pragma unroll
        for (int i = 0; i < 50; i++) sh[w][10 + i] = T[i];
    }
    __syncthreads();
    int nwarps = blockDim.x >> 5;
    if (threadIdx.x < 60) {
        float t = 0.f;
        for (int ww = 0; ww < nwarps; ww++) t += sh[ww][threadIdx.x];
        atomicAdd(&g_red[threadIdx.x], t);
    }
}

// ---------------------------------------------------------------------------
// k_final (1 warp): assemble layer-2 sum, mean pool, MLP, sigmoid.
// ---------------------------------------------------------------------------
__global__ void k_final(const float* __restrict__ Wr2, const float* __restrict__ bb2,
                        const float* __restrict__ W2e, const float* __restrict__ b2e,
                        const float* __restrict__ w1, const float* __restrict__ bw1,
                        const float* __restrict__ w2, const float* __restrict__ bw2,
                        const float* __restrict__ w3, const float* __restrict__ bw3,
                        float* __restrict__ out, int n, int out_size)
{
    __shared__ float g[8];
    int lane = threadIdx.x;
    float invn = 1.0f / (float)n;

    if (lane < 7) {
        int o = lane;
        float s = (float)n * bb2[o];
        #pragma unroll
        for (int i = 0; i < 10; i++) {
            float vi = g_red[i];
            s += vi * Wr2[i * 7 + o];
            float* Ti = &g_red[10 + i * 5];
            int r = i * 7 + o;
            #pragma unroll
            for (int k = 0; k < 4; k++) s += Ti[k] * W2e[r * 4 + k];
            s += Ti[4] * b2e[r];
        }
        g[o] = s * invn;
    }
    __syncwarp();

    if (lane == 0) {
        float gg[7];
        #pragma unroll
        for (int k = 0; k < 7; k++) gg[k] = g[k];
        float g1[20];
        for (int j = 0; j < 20; j++) {
            float v = bw1[j];
            #pragma unroll
            for (int k = 0; k < 7; k++) v += gg[k] * w1[j * 7 + k];
            g1[j] = v > 0.f ? v : 0.f;
        }
        float g2[10];
        for (int j = 0; j < 10; j++) {
            float v = bw2[j];
            #pragma unroll
            for (int k = 0; k < 20; k++) v += g1[k] * w2[j * 20 + k];
            g2[j] = v > 0.f ? v : 0.f;
        }
        float z = bw3[0];
        #pragma unroll
        for (int k = 0; k < 10; k++) z += g2[k] * w3[k];
        float r = 1.0f / (1.0f + expf(-z));
        for (int i = 0; i < out_size; i++) out[i] = r;
    }
}

// ---------------------------------------------------------------------------
extern "C" void kernel_launch(void* const* d_in, const int* in_sizes, int n_in,
                              void* d_out, int out_size)
{
    const float*  x    = (const float*)d_in[0];
    const void*   ei   = d_in[1];
    const float4* attr = (const float4*)d_in[2];
    const float* W1e = (const float*)d_in[3];
    const float* b1e = (const float*)d_in[4];
    const float* Wr1 = (const float*)d_in[5];
    const float* bb1 = (const float*)d_in[6];
    const float* W2e = (const float*)d_in[7];
    const float* b2e = (const float*)d_in[8];
    const float* Wr2 = (const float*)d_in[9];
    const float* bb2 = (const float*)d_in[10];
    const float* w1  = (const float*)d_in[11];
    const float* bw1 = (const float*)d_in[12];
    const float* w2  = (const float*)d_in[13];
    const float* bw2 = (const float*)d_in[14];
    const float* w3  = (const float*)d_in[15];
    const float* bw3 = (const float*)d_in[16];

    int n = in_sizes[0] / 18;
    int e = in_sizes[2] / 4;
    if (n > NN) n = NN;
    if (e > NE) e = NE;

    const int T = 256;
    k_detect<<<1, 128>>>(ei, e, n);
    k_node1<<<(2 * n + T - 1) / T, T>>>(x, W1e, b1e, Wr1, bb1, n);
    k_edge1<<<(e + T - 1) / T, T>>>(ei, attr, e);
    k_reduce2<<<112, T>>>(n);
    k_final<<<1, 32>>>(Wr2, bb2, W2e, b2e, w1, bw1, w2, bw2, w3, bw3,
                       (float*)d_out, n, out_size);
}

// round 5
// speedup vs baseline: 1.5229x; 1.0048x over previous
#include <cuda_runtime.h>
#include <cuda_fp16.h>

#define NN 100000
#define NE 1000000

// Scratch.
// P1h: fp16 table, one 128B row per node: halfs[0..39]=P1[o*4+k], halfs[40..49]=Q1[o]
// g_h1: root1 term per node, 16-float rows (cols 0..9 used). NEVER scattered to.
// g_S : per node: attr-sum[0..3], out-degree at [4] (8-float rows)
__device__ float4 g_P1h[(size_t)NN * 8];
__device__ float4 g_h1 [(size_t)NN * 4];
__device__ float4 g_S  [(size_t)NN * 2];
__device__ float  g_red[64];  // v[i]=g_red[i] (i<10); T[i][k]=g_red[10+i*5+k] (k<5, k==4 deg)
__device__ int    g_is64;

// ---------------------------------------------------------------------------
__global__ void k_detect(const void* __restrict__ ei, int ec, int n)
{
    __shared__ int ok;
    int tid = threadIdx.x;
    if (tid == 0) ok = 1;
    __syncthreads();
    const long long* p = (const long long*)ei;
    int m = ec < 64 ? ec : 64;
    if (tid < 2 * m) {
        long long v = (tid < m) ? p[tid] : p[(size_t)ec + (tid - m)];
        if (v < 0 || v >= n) ok = 0;
    }
    __syncthreads();
    if (tid == 0) g_is64 = ok;
}

__device__ __forceinline__ void load_edge(const void* ei, int ec, int e,
                                          int& src, int& tgt)
{
    if (g_is64) {
        const long long* p = (const long long*)ei;
        src = (int)__ldg(&p[e]);
        tgt = (int)__ldg(&p[(size_t)ec + e]);
    } else {
        const int* p = (const int*)ei;
        src = __ldg(&p[e]);
        tgt = __ldg(&p[(size_t)ec + e]);
    }
}

__device__ __forceinline__ int load_src(const void* ei, int e)
{
    if (g_is64) return (int)__ldg(&((const long long*)ei)[e]);
    return __ldg(&((const int*)ei)[e]);
}

// ---------------------------------------------------------------------------
// k_node1: 2 threads per node, each computes 5 output chans:
//   root1[n][o] = sum_i x[n][i]*Wr1[i][o] + bb1[o]   (f32, to g_h1)
//   P1h / Q1h (fp16 table). Zeroes S rows and g_red.
// ---------------------------------------------------------------------------
__global__ void k_node1(const float* __restrict__ x,
                        const float* __restrict__ W1e, const float* __restrict__ b1e,
                        const float* __restrict__ Wr1, const float* __restrict__ bb1,
                        int n)
{
    __shared__ float sW[720], sB[180], sWr[180], sBB[16];
    for (int i = threadIdx.x; i < 720; i += blockDim.x) sW[i] = W1e[i];
    for (int i = threadIdx.x; i < 180; i += blockDim.x) { sB[i] = b1e[i]; sWr[i] = Wr1[i]; }
    if (threadIdx.x < 10) sBB[threadIdx.x] = bb1[threadIdx.x];
    if (blockIdx.x == 0 && threadIdx.x < 64) g_red[threadIdx.x] = 0.f;
    __syncthreads();

    int gid  = blockIdx.x * blockDim.x + threadIdx.x;
    int nd   = gid >> 1;
    int half = gid & 1;
    if (nd >= n) return;

    float xv[18];
    const float* xr = x + (size_t)nd * 18;
    #pragma unroll
    for (int i = 0; i < 18; i++) xv[i] = __ldg(&xr[i]);

    __half2* prow = (__half2*)(g_P1h + (size_t)nd * 8);
    __half*  qrow = (__half*)prow;
    float*   hrow = (float*)(g_h1 + (size_t)nd * 4);
    float*   srow = (float*)(g_S  + (size_t)nd * 2);

    if (half == 0) {
        *(float4*)srow = make_float4(0.f, 0.f, 0.f, 0.f);
    } else {
        srow[4] = 0.f;
    }

    int o0 = half * 5;
    #pragma unroll
    for (int oo = 0; oo < 5; oo++) {
        int o = o0 + oo;
        float p0 = 0.f, p1 = 0.f, p2 = 0.f, p3 = 0.f, q = 0.f, h = 0.f;
        #pragma unroll
        for (int i = 0; i < 18; i++) {
            int r = i * 10 + o;
            float xi = xv[i];
            p0 += xi * sW[r * 4 + 0];
            p1 += xi * sW[r * 4 + 1];
            p2 += xi * sW[r * 4 + 2];
            p3 += xi * sW[r * 4 + 3];
            q  += xi * sB[r];
            h  += xi * sWr[r];
        }
        prow[o * 2 + 0] = __floats2half2_rn(p0, p1);
        prow[o * 2 + 1] = __floats2half2_rn(p2, p3);
        qrow[40 + o]    = __float2half_rn(q);
        hrow[o]         = h + sBB[o];
    }
}

// ---------------------------------------------------------------------------
// k_edgeS: per edge, RED attr into S[src][0..3] and 1.0 into S[src][4].
// Only remaining per-edge atomics in the whole pipeline (5 f32 elements).
// ---------------------------------------------------------------------------
__global__ void k_edgeS(const void* __restrict__ ei,
                        const float4* __restrict__ attr, int ec)
{
    int e = blockIdx.x * blockDim.x + threadIdx.x;
    if (e >= ec) return;
    int src = load_src(ei, e);
    float4 a = __ldg(&attr[e]);
    float* s = (float*)(g_S + (size_t)src * 2);
    asm volatile("red.global.add.v4.f32 [%0], {%1,%2,%3,%4};"
                 :: "l"(s), "f"(a.x), "f"(a.y), "f"(a.z), "f"(a.w) : "memory");
    asm volatile("red.global.add.f32 [%0], %1;"
                 :: "l"(s + 4), "f"(1.0f) : "memory");
}

// ---------------------------------------------------------------------------
// k_redroot: root contribution over nodes:
//   v[i] += sum_n root1[n][i];  T[i][k] += sum_n root1[n][i]*S[n][k]
// ---------------------------------------------------------------------------
__global__ void k_redroot(int n)
{
    float v[10];
    float T[50];
    #pragma unroll
    for (int i = 0; i < 10; i++) v[i] = 0.f;
    #pragma unroll
    for (int i = 0; i < 50; i++) T[i] = 0.f;

    for (int nd = blockIdx.x * blockDim.x + threadIdx.x; nd < n;
         nd += gridDim.x * blockDim.x) {
        const float* hr = (const float*)(g_h1 + (size_t)nd * 4);
        const float* sr = (const float*)(g_S  + (size_t)nd * 2);
        float4 ha = *(const float4*)hr;
        float4 hb = *(const float4*)(hr + 4);
        float2 hc = *(const float2*)(hr + 8);
        float hv[10] = {ha.x, ha.y, ha.z, ha.w, hb.x, hb.y, hb.z, hb.w, hc.x, hc.y};
        float4 s4 = *(const float4*)sr;
        float  sd = sr[4];
        float sv[5] = {s4.x, s4.y, s4.z, s4.w, sd};
        #pragma unroll
        for (int i = 0; i < 10; i++) {
            float hi = hv[i];
            v[i] += hi;
            #pragma unroll
            for (int k = 0; k < 5; k++) T[i * 5 + k] += hi * sv[k];
        }
    }

    #pragma unroll
    for (int off = 16; off > 0; off >>= 1) {
        #pragma unroll
        for (int i = 0; i < 10; i++) v[i] += __shfl_down_sync(0xffffffffu, v[i], off);
        #pragma unroll
        for (int i = 0; i < 50; i++) T[i] += __shfl_down_sync(0xffffffffu, T[i], off);
    }

    __shared__ float sh[8][64];
    int w = threadIdx.x >> 5, l = threadIdx.x & 31;
    if (l == 0) {
        #pragma unroll
        for (int i = 0; i < 10; i++) sh[w][i] = v[i];
        #pragma unroll
        for (int i = 0; i < 50; i++) sh[w][10 + i] = T[i];
    }
    __syncthreads();
    int nwarps = blockDim.x >> 5;
    if (threadIdx.x < 60) {
        float t = 0.f;
        for (int ww = 0; ww < nwarps; ww++) t += sh[ww][threadIdx.x];
        atomicAdd(&g_red[threadIdx.x], t);
    }
}

// ---------------------------------------------------------------------------
// k_edgeT: message contribution over edges (no per-edge atomics):
//   msg[i] = Q1[src][i] + sum_j attr[e][j]*P1[src][i][j]
//   v[i] += msg[i];  T[i][k] += msg[i]*S[tgt][k]
// Register-accumulated over grid-stride, block-reduced at the end.
// ---------------------------------------------------------------------------
__global__ void k_edgeT(const void* __restrict__ ei,
                        const float4* __restrict__ attr, int ec)
{
    float v[10];
    float T[50];
    #pragma unroll
    for (int i = 0; i < 10; i++) v[i] = 0.f;
    #pragma unroll
    for (int i = 0; i < 50; i++) T[i] = 0.f;

    for (int e = blockIdx.x * blockDim.x + threadIdx.x; e < ec;
         e += gridDim.x * blockDim.x) {
        int src, tgt;
        load_edge(ei, ec, e, src, tgt);
        float4 a = __ldg(&attr[e]);

        const float4* r = g_P1h + (size_t)src * 8;
        float4 raw[7];
        #pragma unroll
        for (int i = 0; i < 6; i++) raw[i] = __ldg(&r[i]);
        raw[6].x = __ldg((const float*)r + 24);
        const __half2* hp = (const __half2*)raw;

        float m[10];
        #pragma unroll
        for (int o = 0; o < 10; o++) {
            float2 pab = __half22float2(hp[o * 2 + 0]);
            float2 pcd = __half22float2(hp[o * 2 + 1]);
            m[o] = a.x * pab.x + a.y * pab.y + a.z * pcd.x + a.w * pcd.y;
        }
        #pragma unroll
        for (int j = 0; j < 5; j++) {
            float2 q2 = __half22float2(hp[20 + j]);
            m[j * 2 + 0] += q2.x;
            m[j * 2 + 1] += q2.y;
        }

        const float* sr = (const float*)(g_S + (size_t)tgt * 2);
        float4 s4 = __ldg((const float4*)sr);
        float  sd = __ldg(sr + 4);

        #pragma unroll
        for (int i = 0; i < 10; i++) {
            float mi = m[i];
            v[i] += mi;
            T[i * 5 + 0] += mi * s4.x;
            T[i * 5 + 1] += mi * s4.y;
            T[i * 5 + 2] += mi * s4.z;
            T[i * 5 + 3] += mi * s4.w;
            T[i * 5 + 4] += mi * sd;
        }
    }

    #pragma unroll
    for (int off = 16; off > 0; off >>= 1) {
        #pragma unroll
        for (int i = 0; i < 10; i++) v[i] += __shfl_down_sync(0xffffffffu, v[i], off);
        #pragma unroll
        for (int i = 0; i < 50; i++) T[i] += __shfl_down_sync(0xffffffffu, T[i], off);
    }

    __shared__ float sh[8][64];
    int w = threadIdx.x >> 5, l = threadIdx.x & 31;
    if (l == 0) {
        #pragma unroll
        for (int i = 0; i < 10; i++) sh[w][i] = v[i];
        #pragma unroll
        for (int i = 0; i < 50; i++) sh[w][10 + i] = T[i];
    }
    __syncthreads();
    int nwarps = blockDim.x >> 5;
    if (threadIdx.x < 60) {
        float t = 0.f;
        for (int ww = 0; ww < nwarps; ww++) t += sh[ww][threadIdx.x];
        atomicAdd(&g_red[threadIdx.x], t);
    }
}

// ---------------------------------------------------------------------------
// k_final (1 warp): assemble layer-2 sum, mean pool, MLP, sigmoid.
// ---------------------------------------------------------------------------
__global__ void k_final(const float* __restrict__ Wr2, const float* __restrict__ bb2,
                        const float* __restrict__ W2e, const float* __restrict__ b2e,
                        const float* __restrict__ w1, const float* __restrict__ bw1,
                        const float* __restrict__ w2, const float* __restrict__ bw2,
                        const float* __restrict__ w3, const float* __restrict__ bw3,
                        float* __restrict__ out, int n, int out_size)
{
    __shared__ float g[8];
    int lane = threadIdx.x;
    float invn = 1.0f / (float)n;

    if (lane < 7) {
        int o = lane;
        float s = (float)n * bb2[o];
        #pragma unroll
        for (int i = 0; i < 10; i++) {
            float vi = g_red[i];
            s += vi * Wr2[i * 7 + o];
            float* Ti = &g_red[10 + i * 5];
            int r = i * 7 + o;
            #pragma unroll
            for (int k = 0; k < 4; k++) s += Ti[k] * W2e[r * 4 + k];
            s += Ti[4] * b2e[r];
        }
        g[o] = s * invn;
    }
    __syncwarp();

    if (lane == 0) {
        float gg[7];
        #pragma unroll
        for (int k = 0; k < 7; k++) gg[k] = g[k];
        float g1[20];
        for (int j = 0; j < 20; j++) {
            float v = bw1[j];
            #pragma unroll
            for (int k = 0; k < 7; k++) v += gg[k] * w1[j * 7 + k];
            g1[j] = v > 0.f ? v : 0.f;
        }
        float g2[10];
        for (int j = 0; j < 10; j++) {
            float v = bw2[j];
            #pragma unroll
            for (int k = 0; k < 20; k++) v += g1[k] * w2[j * 20 + k];
            g2[j] = v > 0.f ? v : 0.f;
        }
        float z = bw3[0];
        #pragma unroll
        for (int k = 0; k < 10; k++) z += g2[k] * w3[k];
        float r = 1.0f / (1.0f + expf(-z));
        for (int i = 0; i < out_size; i++) out[i] = r;
    }
}

// ---------------------------------------------------------------------------
extern "C" void kernel_launch(void* const* d_in, const int* in_sizes, int n_in,
                              void* d_out, int out_size)
{
    const float*  x    = (const float*)d_in[0];
    const void*   ei   = d_in[1];
    const float4* attr = (const float4*)d_in[2];
    const float* W1e = (const float*)d_in[3];
    const float* b1e = (const float*)d_in[4];
    const float* Wr1 = (const float*)d_in[5];
    const float* bb1 = (const float*)d_in[6];
    const float* W2e = (const float*)d_in[7];
    const float* b2e = (const float*)d_in[8];
    const float* Wr2 = (const float*)d_in[9];
    const float* bb2 = (const float*)d_in[10];
    const float* w1  = (const float*)d_in[11];
    const float* bw1 = (const float*)d_in[12];
    const float* w2  = (const float*)d_in[13];
    const float* bw2 = (const float*)d_in[14];
    const float* w3  = (const float*)d_in[15];
    const float* bw3 = (const float*)d_in[16];

    int n = in_sizes[0] / 18;
    int e = in_sizes[2] / 4;
    if (n > NN) n = NN;
    if (e > NE) e = NE;

    const int T = 256;
    k_detect<<<1, 128>>>(ei, e, n);
    k_node1<<<(2 * n + T - 1) / T, T>>>(x, W1e, b1e, Wr1, bb1, n);
    k_edgeS<<<(e + T - 1) / T, T>>>(ei, attr, e);
    k_redroot<<<148, T>>>(n);
    k_edgeT<<<296, T>>>(ei, attr, e);
    k_final<<<1, 32>>>(Wr2, bb2, W2e, b2e, w1, bw1, w2, bw2, w3, bw3,
                       (float*)d_out, n, out_size);
}

// round 6
// speedup vs baseline: 1.7235x; 1.1317x over previous
#include <cuda_runtime.h>
#include <cuda_fp16.h>

#define NN 100000
#define NE 1000000

// Scratch.
// P1h: fp16 table, one 128B row per node: halfs[0..39]=P1[o*4+k], halfs[40..49]=Q1[o]
// g_h1: root1 term per node, 16-float rows (cols 0..9 used)
// g_S : per node: attr-sum[0..3], out-degree at [4] (8-float rows)
__device__ float4 g_P1h[(size_t)NN * 8];
__device__ float4 g_h1 [(size_t)NN * 4];
__device__ float4 g_S  [(size_t)NN * 2];
__device__ float  g_red[64];  // v[i]=g_red[i] (i<10); T[i][k]=g_red[10+i*5+k]
__device__ int    g_is64;
__device__ unsigned int g_count;

// ---------------------------------------------------------------------------
// k_zero: zero S rows + g_red + counter; detect edge_index dtype (block 0).
// Detection reads only the FIRST ec-half (always in-bounds for both dtypes).
// ---------------------------------------------------------------------------
__global__ void k_zero(const void* __restrict__ ei, int ec, int n)
{
    int tid = blockIdx.x * blockDim.x + threadIdx.x;
    int tot = gridDim.x * blockDim.x;
    float4 z = make_float4(0.f, 0.f, 0.f, 0.f);
    for (int i = tid; i < 2 * n; i += tot) g_S[i] = z;
    if (blockIdx.x == 0) {
        if (threadIdx.x < 64) g_red[threadIdx.x] = 0.f;
        if (threadIdx.x == 64) g_count = 0u;
        __shared__ int ok;
        if (threadIdx.x == 0) ok = 1;
        __syncthreads();
        const long long* p = (const long long*)ei;
        int m = ec < 128 ? ec : 128;
        if (threadIdx.x < m) {
            long long v = p[threadIdx.x];
            if (v < 0 || v >= n) ok = 0;
        }
        __syncthreads();
        if (threadIdx.x == 0) g_is64 = ok;
    }
}

__device__ __forceinline__ void load_edge(const void* ei, int ec, int e,
                                          int& src, int& tgt, int is64)
{
    if (is64) {
        const long long* p = (const long long*)ei;
        src = (int)__ldg(&p[e]);
        tgt = (int)__ldg(&p[(size_t)ec + e]);
    } else {
        const int* p = (const int*)ei;
        src = __ldg(&p[e]);
        tgt = __ldg(&p[(size_t)ec + e]);
    }
}

// ---------------------------------------------------------------------------
// k_mid: block-role split.
//  blocks [0, nodeBlocks): node role — 128 nodes/block, 2 threads/node:
//    root1[n][o] (f32 to g_h1), P1h/Q1h (fp16 table). x staged via smem.
//  blocks [nodeBlocks, ...): edge role — RED attr into S[src][0..3], 1->S[src][4]
// Roles are independent (S pre-zeroed by k_zero) => latency/atomic overlap.
// ---------------------------------------------------------------------------
__global__ void k_mid(const float* __restrict__ x,
                      const float* __restrict__ W1e, const float* __restrict__ b1e,
                      const float* __restrict__ Wr1, const float* __restrict__ bb1,
                      const void* __restrict__ ei, const float4* __restrict__ attr,
                      int n, int ec, int nodeBlocks)
{
    if (blockIdx.x >= nodeBlocks) {
        // ---- edge role: build S ----
        int e = (blockIdx.x - nodeBlocks) * blockDim.x + threadIdx.x;
        if (e >= ec) return;
        int src;
        if (g_is64) src = (int)__ldg(&((const long long*)ei)[e]);
        else        src = __ldg(&((const int*)ei)[e]);
        float4 a = __ldg(&attr[e]);
        float* s = (float*)(g_S + (size_t)src * 2);
        asm volatile("red.global.add.v4.f32 [%0], {%1,%2,%3,%4};"
                     :: "l"(s), "f"(a.x), "f"(a.y), "f"(a.z), "f"(a.w) : "memory");
        asm volatile("red.global.add.f32 [%0], %1;"
                     :: "l"(s + 4), "f"(1.0f) : "memory");
        return;
    }

    // ---- node role ----
    __shared__ float sW[720], sB[180], sWr[180], sBB[16];
    __shared__ float sx[128 * 18];
    for (int i = threadIdx.x; i < 720; i += blockDim.x) sW[i] = W1e[i];
    for (int i = threadIdx.x; i < 180; i += blockDim.x) { sB[i] = b1e[i]; sWr[i] = Wr1[i]; }
    if (threadIdx.x < 10) sBB[threadIdx.x] = bb1[threadIdx.x];

    int nd0 = blockIdx.x * 128;
    int cnt = n - nd0; if (cnt > 128) cnt = 128;
    for (int i = threadIdx.x; i < cnt * 18; i += blockDim.x)
        sx[i] = __ldg(&x[(size_t)nd0 * 18 + i]);
    __syncthreads();

    int ndl  = threadIdx.x >> 1;
    int half = threadIdx.x & 1;
    if (ndl >= cnt) return;
    int nd = nd0 + ndl;

    float xv[18];
    #pragma unroll
    for (int i = 0; i < 18; i++) xv[i] = sx[ndl * 18 + i];

    __half2* prow = (__half2*)(g_P1h + (size_t)nd * 8);
    __half*  qrow = (__half*)prow;
    float*   hrow = (float*)(g_h1 + (size_t)nd * 4);

    int o0 = half * 5;
    #pragma unroll
    for (int oo = 0; oo < 5; oo++) {
        int o = o0 + oo;
        float p0 = 0.f, p1 = 0.f, p2 = 0.f, p3 = 0.f, q = 0.f, h = 0.f;
        #pragma unroll
        for (int i = 0; i < 18; i++) {
            int r = i * 10 + o;
            float xi = xv[i];
            p0 += xi * sW[r * 4 + 0];
            p1 += xi * sW[r * 4 + 1];
            p2 += xi * sW[r * 4 + 2];
            p3 += xi * sW[r * 4 + 3];
            q  += xi * sB[r];
            h  += xi * sWr[r];
        }
        prow[o * 2 + 0] = __floats2half2_rn(p0, p1);
        prow[o * 2 + 1] = __floats2half2_rn(p2, p3);
        qrow[40 + o]    = __float2half_rn(q);
        hrow[o]         = h + sBB[o];
    }
}

// ---------------------------------------------------------------------------
// k_tail: phase1 streams nodes (root1 x S), phase2 grid-strides edges
// (msg x S[tgt]); one block-reduce tail -> g_red atomics; last block runs the
// pool + MLP + sigmoid and writes out.
// ---------------------------------------------------------------------------
__global__ void k_tail(const void* __restrict__ ei, const float4* __restrict__ attr,
                       const float* __restrict__ Wr2, const float* __restrict__ bb2,
                       const float* __restrict__ W2e, const float* __restrict__ b2e,
                       const float* __restrict__ w1, const float* __restrict__ bw1,
                       const float* __restrict__ w2, const float* __restrict__ bw2,
                       const float* __restrict__ w3, const float* __restrict__ bw3,
                       float* __restrict__ out, int n, int ec, int out_size)
{
    float v[10];
    float T[50];
    #pragma unroll
    for (int i = 0; i < 10; i++) v[i] = 0.f;
    #pragma unroll
    for (int i = 0; i < 50; i++) T[i] = 0.f;

    int stride = gridDim.x * blockDim.x;
    int g0 = blockIdx.x * blockDim.x + threadIdx.x;

    // ---- phase 1: root contribution (streaming) ----
    for (int nd = g0; nd < n; nd += stride) {
        const float* hr = (const float*)(g_h1 + (size_t)nd * 4);
        const float* sr = (const float*)(g_S  + (size_t)nd * 2);
        float4 ha = *(const float4*)hr;
        float4 hb = *(const float4*)(hr + 4);
        float2 hc = *(const float2*)(hr + 8);
        float hv[10] = {ha.x, ha.y, ha.z, ha.w, hb.x, hb.y, hb.z, hb.w, hc.x, hc.y};
        float4 s4 = *(const float4*)sr;
        float  sd = sr[4];
        #pragma unroll
        for (int i = 0; i < 10; i++) {
            float hi = hv[i];
            v[i] += hi;
            T[i * 5 + 0] += hi * s4.x;
            T[i * 5 + 1] += hi * s4.y;
            T[i * 5 + 2] += hi * s4.z;
            T[i * 5 + 3] += hi * s4.w;
            T[i * 5 + 4] += hi * sd;
        }
    }

    // ---- phase 2: message contribution (gather, no atomics) ----
    int is64 = g_is64;
    for (int e = g0; e < ec; e += stride) {
        int src, tgt;
        load_edge(ei, ec, e, src, tgt, is64);
        float4 a = __ldg(&attr[e]);

        const float4* r = g_P1h + (size_t)src * 8;
        float4 raw[7];
        #pragma unroll
        for (int i = 0; i < 6; i++) raw[i] = __ldg(&r[i]);
        raw[6].x = __ldg((const float*)r + 24);
        const __half2* hp = (const __half2*)raw;

        float m[10];
        #pragma unroll
        for (int o = 0; o < 10; o++) {
            float2 pab = __half22float2(hp[o * 2 + 0]);
            float2 pcd = __half22float2(hp[o * 2 + 1]);
            m[o] = a.x * pab.x + a.y * pab.y + a.z * pcd.x + a.w * pcd.y;
        }
        #pragma unroll
        for (int j = 0; j < 5; j++) {
            float2 q2 = __half22float2(hp[20 + j]);
            m[j * 2 + 0] += q2.x;
            m[j * 2 + 1] += q2.y;
        }

        const float* sr = (const float*)(g_S + (size_t)tgt * 2);
        float4 s4 = __ldg((const float4*)sr);
        float  sd = __ldg(sr + 4);

        #pragma unroll
        for (int i = 0; i < 10; i++) {
            float mi = m[i];
            v[i] += mi;
            T[i * 5 + 0] += mi * s4.x;
            T[i * 5 + 1] += mi * s4.y;
            T[i * 5 + 2] += mi * s4.z;
            T[i * 5 + 3] += mi * s4.w;
            T[i * 5 + 4] += mi * sd;
        }
    }

    // ---- block reduce ----
    #pragma unroll
    for (int off = 16; off > 0; off >>= 1) {
        #pragma unroll
        for (int i = 0; i < 10; i++) v[i] += __shfl_down_sync(0xffffffffu, v[i], off);
        #pragma unroll
        for (int i = 0; i < 50; i++) T[i] += __shfl_down_sync(0xffffffffu, T[i], off);
    }

    __shared__ float sh[8][64];
    int w = threadIdx.x >> 5, l = threadIdx.x & 31;
    if (l == 0) {
        #pragma unroll
        for (int i = 0; i < 10; i++) sh[w][i] = v[i];
        #pragma unroll
        for (int i = 0; i < 50; i++) sh[w][10 + i] = T[i];
    }
    __syncthreads();
    int nwarps = blockDim.x >> 5;
    if (threadIdx.x < 60) {
        float t = 0.f;
        for (int ww = 0; ww < nwarps; ww++) t += sh[ww][threadIdx.x];
        atomicAdd(&g_red[threadIdx.x], t);
    }
    __threadfence();
    __syncthreads();

    // ---- last block: final MLP ----
    __shared__ int isLast;
    if (threadIdx.x == 0) {
        unsigned int prev = atomicAdd(&g_count, 1u);
        isLast = (prev == gridDim.x - 1) ? 1 : 0;
    }
    __syncthreads();
    if (!isLast) return;

    volatile float* gr = g_red;
    __shared__ float g[8];
    int lane = threadIdx.x;
    float invn = 1.0f / (float)n;
    if (lane < 7) {
        int o = lane;
        float s = (float)n * bb2[o];
        #pragma unroll
        for (int i = 0; i < 10; i++) {
            float vi = gr[i];
            s += vi * Wr2[i * 7 + o];
            int r = i * 7 + o;
            #pragma unroll
            for (int k = 0; k < 4; k++) s += gr[10 + i * 5 + k] * W2e[r * 4 + k];
            s += gr[10 + i * 5 + 4] * b2e[r];
        }
        g[o] = s * invn;
    }
    __syncthreads();
    if (lane == 0) {
        float gg[7];
        #pragma unroll
        for (int k = 0; k < 7; k++) gg[k] = g[k];
        float g1[20];
        for (int j = 0; j < 20; j++) {
            float val = bw1[j];
            #pragma unroll
            for (int k = 0; k < 7; k++) val += gg[k] * w1[j * 7 + k];
            g1[j] = val > 0.f ? val : 0.f;
        }
        float g2[10];
        for (int j = 0; j < 10; j++) {
            float val = bw2[j];
            #pragma unroll
            for (int k = 0; k < 20; k++) val += g1[k] * w2[j * 20 + k];
            g2[j] = val > 0.f ? val : 0.f;
        }
        float z = bw3[0];
        #pragma unroll
        for (int k = 0; k < 10; k++) z += g2[k] * w3[k];
        float r = 1.0f / (1.0f + expf(-z));
        for (int i = 0; i < out_size; i++) out[i] = r;
    }
}

// ---------------------------------------------------------------------------
extern "C" void kernel_launch(void* const* d_in, const int* in_sizes, int n_in,
                              void* d_out, int out_size)
{
    const float*  x    = (const float*)d_in[0];
    const void*   ei   = d_in[1];
    const float4* attr = (const float4*)d_in[2];
    const float* W1e = (const float*)d_in[3];
    const float* b1e = (const float*)d_in[4];
    const float* Wr1 = (const float*)d_in[5];
    const float* bb1 = (const float*)d_in[6];
    const float* W2e = (const float*)d_in[7];
    const float* b2e = (const float*)d_in[8];
    const float* Wr2 = (const float*)d_in[9];
    const float* bb2 = (const float*)d_in[10];
    const float* w1  = (const float*)d_in[11];
    const float* bw1 = (const float*)d_in[12];
    const float* w2  = (const float*)d_in[13];
    const float* bw2 = (const float*)d_in[14];
    const float* w3  = (const float*)d_in[15];
    const float* bw3 = (const float*)d_in[16];

    int n = in_sizes[0] / 18;
    int e = in_sizes[2] / 4;
    if (n > NN) n = NN;
    if (e > NE) e = NE;

    const int T = 256;
    int nodeBlocks = (n + 127) / 128;
    int edgeBlocks = (e + T - 1) / T;

    k_zero<<<256, T>>>(ei, e, n);
    k_mid<<<nodeBlocks + edgeBlocks, T>>>(x, W1e, b1e, Wr1, bb1, ei, attr,
                                          n, e, nodeBlocks);
    k_tail<<<296, T>>>(ei, attr, Wr2, bb2, W2e, b2e, w1, bw1, w2, bw2, w3, bw3,
                       (float*)d_out, n, e, out_size);
}